// round 2
// baseline (speedup 1.0000x reference)
#include <cuda_runtime.h>
#include <math.h>

#define N_NODES 100000
#define N_EDGES 1600000
#define MAX_ITER 50

// ---------------- device scratch (static, no allocs) ----------------
__device__ float g_F[(size_t)N_EDGES * 16];   // precomputed b1 + edge_feat@W1[:8], padded to 16
__device__ float g_state[N_NODES * 8];        // padded node state
__device__ float g_old[N_NODES * 8];
__device__ float g_new[N_NODES * 8];          // scatter target, kept zeroed when idle
__device__ int   g_flags[MAX_ITER + 1];
__device__ int   g_num;

// ---------------- constant weights ----------------
__constant__ float cW1a[8 * 15];   // W1 rows 0..7   (edge_feat part)
__constant__ float cW1b[5 * 15];   // W1 rows 8..12  (state part)
__constant__ float cb1[15];
__constant__ float cW2[15 * 5];
__constant__ float cb2[5];
__constant__ float cW3[5 * 10];
__constant__ float cb3[10];
__constant__ float cW4[10 * 7];
__constant__ float cb4[7];

__device__ __forceinline__ float tanh_fast(float x) {
    float y;
    asm("tanh.approx.f32 %0, %1;" : "=f"(y) : "f"(x));
    return y;
}

// ---------------- kernels ----------------
__global__ void init_flags_kernel() {
    int t = threadIdx.x;
    if (t <= MAX_ITER) g_flags[t] = 0;
    if (t == 63) g_num = 0;
}

__global__ __launch_bounds__(256) void init_nodes_kernel(
    const float* __restrict__ state_init,
    const float* __restrict__ old_init)
{
    int i = blockIdx.x * blockDim.x + threadIdx.x;
    bool exceed = false;
    if (i < N_NODES) {
        float d2 = 0.f;
        #pragma unroll
        for (int c = 0; c < 5; c++) {
            float s = state_init[i * 5 + c];
            float o = old_init[i * 5 + c];
            g_state[i * 8 + c] = s;
            g_old[i * 8 + c]   = o;
            g_new[i * 8 + c]   = 0.f;
            float d = s - o;
            d2 += d * d;
        }
        #pragma unroll
        for (int c = 5; c < 8; c++) {
            g_state[i * 8 + c] = 0.f;
            g_old[i * 8 + c]   = 0.f;
            g_new[i * 8 + c]   = 0.f;
        }
        exceed = sqrtf(d2 + 1e-11f) > 0.01f;
    }
    unsigned b = __ballot_sync(0xffffffffu, exceed);
    if ((threadIdx.x & 31) == 0 && b) atomicOr(&g_flags[0], 1);
}

__global__ __launch_bounds__(256) void precompute_kernel(
    const float* __restrict__ edge_feat)
{
    int e = blockIdx.x * blockDim.x + threadIdx.x;
    if (e >= N_EDGES) return;
    const float4* efp = (const float4*)(edge_feat + (size_t)e * 8);
    float4 a0 = efp[0], a1 = efp[1];
    float ef[8] = {a0.x, a0.y, a0.z, a0.w, a1.x, a1.y, a1.z, a1.w};
    float v[16];
    #pragma unroll
    for (int j = 0; j < 15; j++) {
        float acc = cb1[j];
        #pragma unroll
        for (int d = 0; d < 8; d++) acc += ef[d] * cW1a[d * 15 + j];
        v[j] = acc;
    }
    v[15] = 0.f;
    float4* op = (float4*)(g_F + (size_t)e * 16);
    op[0] = make_float4(v[0],  v[1],  v[2],  v[3]);
    op[1] = make_float4(v[4],  v[5],  v[6],  v[7]);
    op[2] = make_float4(v[8],  v[9],  v[10], v[11]);
    op[3] = make_float4(v[12], v[13], v[14], v[15]);
}

__global__ __launch_bounds__(256) void edge_kernel(
    const int*   __restrict__ edge_src,
    const int*   __restrict__ arc_rows,
    const float* __restrict__ arc_vals,
    int k)
{
    if (g_flags[k] == 0) return;   // converged: cheap exit
    int e = blockIdx.x * blockDim.x + threadIdx.x;
    if (e >= N_EDGES) return;

    int src = edge_src[e];
    float4 sa = *(const float4*)(g_state + src * 8);
    float  g4 = g_state[src * 8 + 4];

    const float4* fp = (const float4*)(g_F + (size_t)e * 16);
    float4 f0 = fp[0], f1 = fp[1], f2 = fp[2], f3 = fp[3];
    float fr[15] = {f0.x, f0.y, f0.z, f0.w,
                    f1.x, f1.y, f1.z, f1.w,
                    f2.x, f2.y, f2.z, f2.w,
                    f3.x, f3.y, f3.z};

    float h1[15];
    #pragma unroll
    for (int j = 0; j < 15; j++) {
        float a = fr[j];
        a += sa.x * cW1b[0 * 15 + j];
        a += sa.y * cW1b[1 * 15 + j];
        a += sa.z * cW1b[2 * 15 + j];
        a += sa.w * cW1b[3 * 15 + j];
        a += g4   * cW1b[4 * 15 + j];
        h1[j] = tanh_fast(a);
    }

    float av = arc_vals[e];
    int   r  = arc_rows[e];
    #pragma unroll
    for (int c = 0; c < 5; c++) {
        float a = cb2[c];
        #pragma unroll
        for (int j = 0; j < 15; j++) a += h1[j] * cW2[j * 5 + c];
        atomicAdd(&g_new[r * 8 + c], tanh_fast(a) * av);
    }
}

__global__ __launch_bounds__(256) void update_kernel(int k) {
    if (g_flags[k] == 0) return;   // cond false -> flags[k+1] stays 0, state frozen
    int i = blockIdx.x * blockDim.x + threadIdx.x;
    bool exceed = false;
    if (i < N_NODES) {
        float d2 = 0.f;
        #pragma unroll
        for (int c = 0; c < 5; c++) {
            float ns = g_new[i * 8 + c];
            float st = g_state[i * 8 + c];
            g_old[i * 8 + c]   = st;
            g_state[i * 8 + c] = ns;
            g_new[i * 8 + c]   = 0.f;   // re-zero for next iteration
            float d = ns - st;
            d2 += d * d;
        }
        exceed = sqrtf(d2 + 1e-11f) > 0.01f;
        if (i == 0) g_num += 1;
    }
    unsigned b = __ballot_sync(0xffffffffu, exceed);
    if ((threadIdx.x & 31) == 0 && b) atomicOr(&g_flags[k + 1], 1);
}

__global__ __launch_bounds__(256) void output_kernel(float* __restrict__ out, int out_size) {
    int i = blockIdx.x * blockDim.x + threadIdx.x;
    if (i >= N_NODES) return;

    float s[5];
    #pragma unroll
    for (int c = 0; c < 5; c++) s[c] = g_state[i * 8 + c];

    float o1[10];
    #pragma unroll
    for (int j = 0; j < 10; j++) {
        float a = cb3[j];
        #pragma unroll
        for (int c = 0; c < 5; c++) a += s[c] * cW3[c * 10 + j];
        o1[j] = tanh_fast(a);
    }

    float l[7];
    #pragma unroll
    for (int c = 0; c < 7; c++) {
        float a = cb4[c];
        #pragma unroll
        for (int j = 0; j < 10; j++) a += o1[j] * cW4[j * 7 + c];
        l[c] = a;
    }

    float m = l[0];
    #pragma unroll
    for (int c = 1; c < 7; c++) m = fmaxf(m, l[c]);
    float ex[7];
    float sum = 0.f;
    #pragma unroll
    for (int c = 0; c < 7; c++) { ex[c] = __expf(l[c] - m); sum += ex[c]; }
    float inv = 1.0f / sum;
    #pragma unroll
    for (int c = 0; c < 7; c++) out[i * 7 + c] = ex[c] * inv;

    if (i == 0 && out_size > N_NODES * 7) {
        out[N_NODES * 7] = (float)g_num;   // second tuple output: iteration count
    }
}

// ---------------- launcher (graph-capturable: kernels + D2D memcpys only) ----------------
extern "C" void kernel_launch(void* const* d_in, const int* in_sizes, int n_in,
                              void* d_out, int out_size)
{
    const float* edge_feat  = (const float*)d_in[0];
    const int*   edge_src   = (const int*)  d_in[1];
    const int*   arc_rows   = (const int*)  d_in[2];
    const float* arc_vals   = (const float*)d_in[3];
    const float* state_init = (const float*)d_in[4];
    const float* old_init   = (const float*)d_in[5];
    const float* W1 = (const float*)d_in[6];
    const float* b1 = (const float*)d_in[7];
    const float* W2 = (const float*)d_in[8];
    const float* b2 = (const float*)d_in[9];
    const float* W3 = (const float*)d_in[10];
    const float* b3 = (const float*)d_in[11];
    const float* W4 = (const float*)d_in[12];
    const float* b4 = (const float*)d_in[13];

    // weights -> constant memory (device-to-device, capturable)
    cudaMemcpyToSymbolAsync(cW1a, W1,           8 * 15 * sizeof(float), 0, cudaMemcpyDeviceToDevice, 0);
    cudaMemcpyToSymbolAsync(cW1b, W1 + 8 * 15,  5 * 15 * sizeof(float), 0, cudaMemcpyDeviceToDevice, 0);
    cudaMemcpyToSymbolAsync(cb1,  b1,           15 * sizeof(float),     0, cudaMemcpyDeviceToDevice, 0);
    cudaMemcpyToSymbolAsync(cW2,  W2,           15 * 5 * sizeof(float), 0, cudaMemcpyDeviceToDevice, 0);
    cudaMemcpyToSymbolAsync(cb2,  b2,           5 * sizeof(float),      0, cudaMemcpyDeviceToDevice, 0);
    cudaMemcpyToSymbolAsync(cW3,  W3,           5 * 10 * sizeof(float), 0, cudaMemcpyDeviceToDevice, 0);
    cudaMemcpyToSymbolAsync(cb3,  b3,           10 * sizeof(float),     0, cudaMemcpyDeviceToDevice, 0);
    cudaMemcpyToSymbolAsync(cW4,  W4,           10 * 7 * sizeof(float), 0, cudaMemcpyDeviceToDevice, 0);
    cudaMemcpyToSymbolAsync(cb4,  b4,           7 * sizeof(float),      0, cudaMemcpyDeviceToDevice, 0);

    const int NODE_BLOCKS = (N_NODES + 255) / 256;
    const int EDGE_BLOCKS = (N_EDGES + 255) / 256;

    init_flags_kernel<<<1, 64>>>();
    init_nodes_kernel<<<NODE_BLOCKS, 256>>>(state_init, old_init);
    precompute_kernel<<<EDGE_BLOCKS, 256>>>(edge_feat);

    for (int k = 0; k < MAX_ITER; k++) {
        edge_kernel<<<EDGE_BLOCKS, 256>>>(edge_src, arc_rows, arc_vals, k);
        update_kernel<<<NODE_BLOCKS, 256>>>(k);
    }

    output_kernel<<<NODE_BLOCKS, 256>>>((float*)d_out, out_size);
}

// round 3
// speedup vs baseline: 1.2778x; 1.2778x over previous
#include <cuda_runtime.h>
#include <cuda_fp16.h>
#include <math.h>

#define N_NODES 100000
#define N_EDGES 1600000
#define MAX_ITER 50

// ---------------- device scratch (static, no allocs) ----------------
__device__ __half g_F[(size_t)N_EDGES * 16];  // fp16: b1 + edge_feat@W1[:8], padded to 16
__device__ float g_state[N_NODES * 8];        // padded node state
__device__ float g_old[N_NODES * 8];
__device__ float g_new[N_NODES * 8];          // scatter target, kept zeroed when idle
__device__ int   g_flags[MAX_ITER + 1];
__device__ int   g_num;

// ---------------- constant weights ----------------
__constant__ float cW1a[8 * 15];   // W1 rows 0..7   (edge_feat part)
__constant__ float cW1b[5 * 15];   // W1 rows 8..12  (state part)
__constant__ float cb1[15];
__constant__ float cW2[15 * 5];
__constant__ float cb2[5];
__constant__ float cW3[5 * 10];
__constant__ float cb3[10];
__constant__ float cW4[10 * 7];
__constant__ float cb4[7];

__device__ __forceinline__ float tanh_fast(float x) {
    float y;
    asm("tanh.approx.f32 %0, %1;" : "=f"(y) : "f"(x));
    return y;
}

// ---------------- kernels ----------------
__global__ void init_flags_kernel() {
    int t = threadIdx.x;
    if (t <= MAX_ITER) g_flags[t] = 0;
    if (t == 63) g_num = 0;
}

__global__ __launch_bounds__(256) void init_nodes_kernel(
    const float* __restrict__ state_init,
    const float* __restrict__ old_init)
{
    int i = blockIdx.x * blockDim.x + threadIdx.x;
    bool exceed = false;
    if (i < N_NODES) {
        float d2 = 0.f;
        #pragma unroll
        for (int c = 0; c < 5; c++) {
            float s = state_init[i * 5 + c];
            float o = old_init[i * 5 + c];
            g_state[i * 8 + c] = s;
            g_old[i * 8 + c]   = o;
            g_new[i * 8 + c]   = 0.f;
            float d = s - o;
            d2 += d * d;
        }
        #pragma unroll
        for (int c = 5; c < 8; c++) {
            g_state[i * 8 + c] = 0.f;
            g_old[i * 8 + c]   = 0.f;
            g_new[i * 8 + c]   = 0.f;
        }
        exceed = sqrtf(d2 + 1e-11f) > 0.01f;
    }
    unsigned b = __ballot_sync(0xffffffffu, exceed);
    if ((threadIdx.x & 31) == 0 && b) atomicOr(&g_flags[0], 1);
}

__global__ __launch_bounds__(256) void precompute_kernel(
    const float* __restrict__ edge_feat)
{
    int e = blockIdx.x * blockDim.x + threadIdx.x;
    if (e >= N_EDGES) return;
    const float4* efp = (const float4*)(edge_feat + (size_t)e * 8);
    float4 a0 = efp[0], a1 = efp[1];
    float ef[8] = {a0.x, a0.y, a0.z, a0.w, a1.x, a1.y, a1.z, a1.w};
    float v[16];
    #pragma unroll
    for (int j = 0; j < 15; j++) {
        float acc = cb1[j];
        #pragma unroll
        for (int d = 0; d < 8; d++) acc += ef[d] * cW1a[d * 15 + j];
        v[j] = acc;
    }
    v[15] = 0.f;
    union { float4 v4[2]; __half2 h2[8]; } u;
    #pragma unroll
    for (int j = 0; j < 8; j++)
        u.h2[j] = __floats2half2_rn(v[2 * j], v[2 * j + 1]);
    float4* op = (float4*)(g_F + (size_t)e * 16);
    op[0] = u.v4[0];
    op[1] = u.v4[1];
}

__global__ __launch_bounds__(256) void edge_kernel(
    const int*   __restrict__ edge_src,
    const int*   __restrict__ arc_rows,
    const float* __restrict__ arc_vals,
    int k)
{
    if (g_flags[k] == 0) return;   // converged: cheap exit
    int e = blockIdx.x * blockDim.x + threadIdx.x;
    if (e >= N_EDGES) return;

    int src = edge_src[e];
    float4 sa = *(const float4*)(g_state + src * 8);
    float  g4 = g_state[src * 8 + 4];

    // fp16 F: 32 bytes per edge
    const float4* fp = (const float4*)(g_F + (size_t)e * 16);
    union { float4 v4[2]; __half2 h2[8]; } u;
    u.v4[0] = fp[0];
    u.v4[1] = fp[1];
    float fr[16];
    #pragma unroll
    for (int j = 0; j < 8; j++) {
        float2 t = __half22float2(u.h2[j]);
        fr[2 * j]     = t.x;
        fr[2 * j + 1] = t.y;
    }

    float h1[15];
    #pragma unroll
    for (int j = 0; j < 15; j++) {
        float a = fr[j];
        a += sa.x * cW1b[0 * 15 + j];
        a += sa.y * cW1b[1 * 15 + j];
        a += sa.z * cW1b[2 * 15 + j];
        a += sa.w * cW1b[3 * 15 + j];
        a += g4   * cW1b[4 * 15 + j];
        h1[j] = tanh_fast(a);
    }

    float av = arc_vals[e];
    int   r  = arc_rows[e];
    #pragma unroll
    for (int c = 0; c < 5; c++) {
        float a = cb2[c];
        #pragma unroll
        for (int j = 0; j < 15; j++) a += h1[j] * cW2[j * 5 + c];
        atomicAdd(&g_new[r * 8 + c], tanh_fast(a) * av);
    }
}

__global__ __launch_bounds__(256) void update_kernel(int k) {
    if (g_flags[k] == 0) return;   // cond false -> flags[k+1] stays 0, state frozen
    int i = blockIdx.x * blockDim.x + threadIdx.x;
    bool exceed = false;
    if (i < N_NODES) {
        float4* np = (float4*)(g_new + i * 8);
        float4* sp = (float4*)(g_state + i * 8);
        float4* op = (float4*)(g_old + i * 8);
        float4 n0 = np[0], n1 = np[1];
        float4 s0 = sp[0], s1 = sp[1];
        // old <- state
        op[0] = s0; op[1] = s1;
        // state <- new
        sp[0] = n0; sp[1] = n1;
        // new <- 0
        np[0] = make_float4(0.f, 0.f, 0.f, 0.f);
        np[1] = make_float4(0.f, 0.f, 0.f, 0.f);
        float dx = n0.x - s0.x, dy = n0.y - s0.y, dz = n0.z - s0.z,
              dw = n0.w - s0.w, d4 = n1.x - s1.x;
        float d2 = dx * dx + dy * dy + dz * dz + dw * dw + d4 * d4;
        exceed = sqrtf(d2 + 1e-11f) > 0.01f;
        if (i == 0) g_num += 1;
    }
    unsigned b = __ballot_sync(0xffffffffu, exceed);
    if ((threadIdx.x & 31) == 0 && b) atomicOr(&g_flags[k + 1], 1);
}

__global__ __launch_bounds__(256) void output_kernel(float* __restrict__ out, int out_size) {
    int i = blockIdx.x * blockDim.x + threadIdx.x;
    if (i >= N_NODES) return;

    float s[5];
    #pragma unroll
    for (int c = 0; c < 5; c++) s[c] = g_state[i * 8 + c];

    float o1[10];
    #pragma unroll
    for (int j = 0; j < 10; j++) {
        float a = cb3[j];
        #pragma unroll
        for (int c = 0; c < 5; c++) a += s[c] * cW3[c * 10 + j];
        o1[j] = tanh_fast(a);
    }

    float l[7];
    #pragma unroll
    for (int c = 0; c < 7; c++) {
        float a = cb4[c];
        #pragma unroll
        for (int j = 0; j < 10; j++) a += o1[j] * cW4[j * 7 + c];
        l[c] = a;
    }

    float m = l[0];
    #pragma unroll
    for (int c = 1; c < 7; c++) m = fmaxf(m, l[c]);
    float ex[7];
    float sum = 0.f;
    #pragma unroll
    for (int c = 0; c < 7; c++) { ex[c] = __expf(l[c] - m); sum += ex[c]; }
    float inv = 1.0f / sum;
    #pragma unroll
    for (int c = 0; c < 7; c++) out[i * 7 + c] = ex[c] * inv;

    if (i == 0 && out_size > N_NODES * 7) {
        out[N_NODES * 7] = (float)g_num;   // second tuple output: iteration count
    }
}

// ---------------- launcher (graph-capturable: kernels + D2D memcpys only) ----------------
extern "C" void kernel_launch(void* const* d_in, const int* in_sizes, int n_in,
                              void* d_out, int out_size)
{
    const float* edge_feat  = (const float*)d_in[0];
    const int*   edge_src   = (const int*)  d_in[1];
    const int*   arc_rows   = (const int*)  d_in[2];
    const float* arc_vals   = (const float*)d_in[3];
    const float* state_init = (const float*)d_in[4];
    const float* old_init   = (const float*)d_in[5];
    const float* W1 = (const float*)d_in[6];
    const float* b1 = (const float*)d_in[7];
    const float* W2 = (const float*)d_in[8];
    const float* b2 = (const float*)d_in[9];
    const float* W3 = (const float*)d_in[10];
    const float* b3 = (const float*)d_in[11];
    const float* W4 = (const float*)d_in[12];
    const float* b4 = (const float*)d_in[13];

    // weights -> constant memory (device-to-device, capturable)
    cudaMemcpyToSymbolAsync(cW1a, W1,           8 * 15 * sizeof(float), 0, cudaMemcpyDeviceToDevice, 0);
    cudaMemcpyToSymbolAsync(cW1b, W1 + 8 * 15,  5 * 15 * sizeof(float), 0, cudaMemcpyDeviceToDevice, 0);
    cudaMemcpyToSymbolAsync(cb1,  b1,           15 * sizeof(float),     0, cudaMemcpyDeviceToDevice, 0);
    cudaMemcpyToSymbolAsync(cW2,  W2,           15 * 5 * sizeof(float), 0, cudaMemcpyDeviceToDevice, 0);
    cudaMemcpyToSymbolAsync(cb2,  b2,           5 * sizeof(float),      0, cudaMemcpyDeviceToDevice, 0);
    cudaMemcpyToSymbolAsync(cW3,  W3,           5 * 10 * sizeof(float), 0, cudaMemcpyDeviceToDevice, 0);
    cudaMemcpyToSymbolAsync(cb3,  b3,           10 * sizeof(float),     0, cudaMemcpyDeviceToDevice, 0);
    cudaMemcpyToSymbolAsync(cW4,  W4,           10 * 7 * sizeof(float), 0, cudaMemcpyDeviceToDevice, 0);
    cudaMemcpyToSymbolAsync(cb4,  b4,           7 * sizeof(float),      0, cudaMemcpyDeviceToDevice, 0);

    const int NODE_BLOCKS = (N_NODES + 255) / 256;
    const int EDGE_BLOCKS = (N_EDGES + 255) / 256;

    init_flags_kernel<<<1, 64>>>();
    init_nodes_kernel<<<NODE_BLOCKS, 256>>>(state_init, old_init);
    precompute_kernel<<<EDGE_BLOCKS, 256>>>(edge_feat);

    for (int k = 0; k < MAX_ITER; k++) {
        edge_kernel<<<EDGE_BLOCKS, 256>>>(edge_src, arc_rows, arc_vals, k);
        update_kernel<<<NODE_BLOCKS, 256>>>(k);
    }

    output_kernel<<<NODE_BLOCKS, 256>>>((float*)d_out, out_size);
}

// round 4
// speedup vs baseline: 2.2293x; 1.7447x over previous
#include <cuda_runtime.h>
#include <cuda_fp16.h>
#include <math.h>

#define N_NODES 100000
#define N_EDGES 1600000
#define MAX_ITER 50

// ---------------- device scratch (static, no allocs) ----------------
__device__ __half g_F[(size_t)N_EDGES * 16];  // fp16 F in SORTED edge order, 32B/edge
__device__ int    g_psrc[N_EDGES];            // permuted edge_src (sorted by row)
__device__ int    g_prow[N_EDGES];            // row key per sorted edge
__device__ float  g_pval[N_EDGES];            // permuted arc_vals
__device__ int    g_cnt[N_NODES];             // histogram
__device__ int    g_cursor[N_NODES];          // running offsets (init = exclusive scan)
__device__ int    g_bsum[128];                // block sums for scan
__device__ int    g_bsumx[128];               // scanned block sums
__device__ float  g_state[N_NODES * 8];
__device__ float  g_old[N_NODES * 8];
__device__ float  g_new[N_NODES * 8];
__device__ int    g_flags[MAX_ITER + 1];
__device__ int    g_num;

// ---------------- constant weights ----------------
__constant__ float cW1a[8 * 15];
__constant__ float cW1b[5 * 15];
__constant__ float cb1[15];
__constant__ float cW2[15 * 5];
__constant__ float cb2[5];
__constant__ float cW3[5 * 10];
__constant__ float cb3[10];
__constant__ float cW4[10 * 7];
__constant__ float cb4[7];

__device__ __forceinline__ float tanh_fast(float x) {
    float y;
    asm("tanh.approx.f32 %0, %1;" : "=f"(y) : "f"(x));
    return y;
}

// ---------------- init ----------------
__global__ void init_flags_kernel() {
    int t = threadIdx.x;
    if (t <= MAX_ITER) g_flags[t] = 0;
    if (t == 63) g_num = 0;
}

__global__ __launch_bounds__(256) void init_nodes_kernel(
    const float* __restrict__ state_init,
    const float* __restrict__ old_init)
{
    int i = blockIdx.x * blockDim.x + threadIdx.x;
    bool exceed = false;
    if (i < N_NODES) {
        g_cnt[i] = 0;
        float d2 = 0.f;
        #pragma unroll
        for (int c = 0; c < 5; c++) {
            float s = state_init[i * 5 + c];
            float o = old_init[i * 5 + c];
            g_state[i * 8 + c] = s;
            g_old[i * 8 + c]   = o;
            g_new[i * 8 + c]   = 0.f;
            float d = s - o;
            d2 += d * d;
        }
        #pragma unroll
        for (int c = 5; c < 8; c++) {
            g_state[i * 8 + c] = 0.f;
            g_old[i * 8 + c]   = 0.f;
            g_new[i * 8 + c]   = 0.f;
        }
        exceed = sqrtf(d2 + 1e-11f) > 0.01f;
    }
    unsigned b = __ballot_sync(0xffffffffu, exceed);
    if ((threadIdx.x & 31) == 0 && b) atomicOr(&g_flags[0], 1);
}

// ---------------- counting sort by arc_rows ----------------
__global__ __launch_bounds__(256) void hist_kernel(const int* __restrict__ arc_rows) {
    int e = blockIdx.x * blockDim.x + threadIdx.x;
    if (e < N_EDGES) atomicAdd(&g_cnt[arc_rows[e]], 1);
}

// 98 blocks x 256 threads, 4 elements/thread -> 1024 elems/block
__global__ __launch_bounds__(256) void scanA_kernel() {
    __shared__ int sh[256];
    int t = threadIdx.x, b = blockIdx.x;
    int base = b * 1024 + t * 4;
    int s = 0;
    #pragma unroll
    for (int j = 0; j < 4; j++) {
        int idx = base + j;
        if (idx < N_NODES) s += g_cnt[idx];
    }
    sh[t] = s; __syncthreads();
    for (int off = 1; off < 256; off <<= 1) {
        int v = (t >= off) ? sh[t - off] : 0;
        __syncthreads();
        sh[t] += v;
        __syncthreads();
    }
    if (t == 255) g_bsum[b] = sh[255];
}

__global__ void scanB_kernel(int nblocks) {
    if (threadIdx.x == 0) {
        int acc = 0;
        for (int b = 0; b < nblocks; b++) {
            g_bsumx[b] = acc;
            acc += g_bsum[b];
        }
    }
}

__global__ __launch_bounds__(256) void scanC_kernel() {
    __shared__ int sh[256];
    int t = threadIdx.x, b = blockIdx.x;
    int base = b * 1024 + t * 4;
    int c[4], s = 0;
    #pragma unroll
    for (int j = 0; j < 4; j++) {
        int idx = base + j;
        c[j] = (idx < N_NODES) ? g_cnt[idx] : 0;
        s += c[j];
    }
    sh[t] = s; __syncthreads();
    for (int off = 1; off < 256; off <<= 1) {
        int v = (t >= off) ? sh[t - off] : 0;
        __syncthreads();
        sh[t] += v;
        __syncthreads();
    }
    int excl = g_bsumx[b] + sh[t] - s;
    #pragma unroll
    for (int j = 0; j < 4; j++) {
        int idx = base + j;
        if (idx < N_NODES) g_cursor[idx] = excl;
        excl += c[j];
    }
}

// scatter edges into sorted order + compute F (fused, once per replay)
__global__ __launch_bounds__(256) void scatter_precompute_kernel(
    const float* __restrict__ edge_feat,
    const int*   __restrict__ edge_src,
    const int*   __restrict__ arc_rows,
    const float* __restrict__ arc_vals)
{
    int e = blockIdx.x * blockDim.x + threadIdx.x;
    if (e >= N_EDGES) return;
    int row = arc_rows[e];
    int pos = atomicAdd(&g_cursor[row], 1);
    g_psrc[pos] = edge_src[e];
    g_prow[pos] = row;
    g_pval[pos] = arc_vals[e];

    const float4* efp = (const float4*)(edge_feat + (size_t)e * 8);
    float4 a0 = efp[0], a1 = efp[1];
    float ef[8] = {a0.x, a0.y, a0.z, a0.w, a1.x, a1.y, a1.z, a1.w};
    float v[16];
    #pragma unroll
    for (int j = 0; j < 15; j++) {
        float acc = cb1[j];
        #pragma unroll
        for (int d = 0; d < 8; d++) acc += ef[d] * cW1a[d * 15 + j];
        v[j] = acc;
    }
    v[15] = 0.f;
    union { float4 v4[2]; __half2 h2[8]; } u;
    #pragma unroll
    for (int j = 0; j < 8; j++)
        u.h2[j] = __floats2half2_rn(v[2 * j], v[2 * j + 1]);
    float4* op = (float4*)(g_F + (size_t)pos * 16);
    op[0] = u.v4[0];
    op[1] = u.v4[1];
}

// ---------------- per-iteration kernels ----------------
__global__ __launch_bounds__(256) void edge_kernel(int k)
{
    if (g_flags[k] == 0) return;
    int e = blockIdx.x * blockDim.x + threadIdx.x;   // grid exactly covers N_EDGES

    int   src = g_psrc[e];
    int   row = g_prow[e];
    float av  = g_pval[e];

    float4 sa = *(const float4*)(g_state + src * 8);
    float  g4 = g_state[src * 8 + 4];

    const float4* fp = (const float4*)(g_F + (size_t)e * 16);
    union { float4 v4[2]; __half2 h2[8]; } u;
    u.v4[0] = fp[0];
    u.v4[1] = fp[1];
    float fr[16];
    #pragma unroll
    for (int j = 0; j < 8; j++) {
        float2 t = __half22float2(u.h2[j]);
        fr[2 * j]     = t.x;
        fr[2 * j + 1] = t.y;
    }

    float h1[15];
    #pragma unroll
    for (int j = 0; j < 15; j++) {
        float a = fr[j];
        a += sa.x * cW1b[0 * 15 + j];
        a += sa.y * cW1b[1 * 15 + j];
        a += sa.z * cW1b[2 * 15 + j];
        a += sa.w * cW1b[3 * 15 + j];
        a += g4   * cW1b[4 * 15 + j];
        h1[j] = tanh_fast(a);
    }

    float v[5];
    #pragma unroll
    for (int c = 0; c < 5; c++) {
        float a = cb2[c];
        #pragma unroll
        for (int j = 0; j < 15; j++) a += h1[j] * cW2[j * 5 + c];
        v[c] = tanh_fast(a) * av;
    }

    // warp-segmented suffix reduction over contiguous equal-row runs
    const unsigned FULL = 0xffffffffu;
    int lane = threadIdx.x & 31;
    int prow = __shfl_up_sync(FULL, row, 1);
    bool head = (lane == 0) || (prow != row);

    #pragma unroll
    for (int off = 1; off < 32; off <<= 1) {
        int r2 = __shfl_down_sync(FULL, row, off);
        bool ok = (lane + off < 32) && (r2 == row);
        #pragma unroll
        for (int c = 0; c < 5; c++) {
            float t = __shfl_down_sync(FULL, v[c], off);
            if (ok) v[c] += t;
        }
    }

    if (head) {
        #pragma unroll
        for (int c = 0; c < 5; c++)
            atomicAdd(&g_new[row * 8 + c], v[c]);
    }
}

__global__ __launch_bounds__(256) void update_kernel(int k) {
    if (g_flags[k] == 0) return;
    int i = blockIdx.x * blockDim.x + threadIdx.x;
    bool exceed = false;
    if (i < N_NODES) {
        float4* np = (float4*)(g_new + i * 8);
        float4* sp = (float4*)(g_state + i * 8);
        float4* op = (float4*)(g_old + i * 8);
        float4 n0 = np[0], n1 = np[1];
        float4 s0 = sp[0], s1 = sp[1];
        op[0] = s0; op[1] = s1;
        sp[0] = n0; sp[1] = n1;
        np[0] = make_float4(0.f, 0.f, 0.f, 0.f);
        np[1] = make_float4(0.f, 0.f, 0.f, 0.f);
        float dx = n0.x - s0.x, dy = n0.y - s0.y, dz = n0.z - s0.z,
              dw = n0.w - s0.w, d4 = n1.x - s1.x;
        float d2 = dx * dx + dy * dy + dz * dz + dw * dw + d4 * d4;
        exceed = sqrtf(d2 + 1e-11f) > 0.01f;
        if (i == 0) g_num += 1;
    }
    unsigned b = __ballot_sync(0xffffffffu, exceed);
    if ((threadIdx.x & 31) == 0 && b) atomicOr(&g_flags[k + 1], 1);
}

__global__ __launch_bounds__(256) void output_kernel(float* __restrict__ out, int out_size) {
    int i = blockIdx.x * blockDim.x + threadIdx.x;
    if (i >= N_NODES) return;

    float s[5];
    #pragma unroll
    for (int c = 0; c < 5; c++) s[c] = g_state[i * 8 + c];

    float o1[10];
    #pragma unroll
    for (int j = 0; j < 10; j++) {
        float a = cb3[j];
        #pragma unroll
        for (int c = 0; c < 5; c++) a += s[c] * cW3[c * 10 + j];
        o1[j] = tanh_fast(a);
    }

    float l[7];
    #pragma unroll
    for (int c = 0; c < 7; c++) {
        float a = cb4[c];
        #pragma unroll
        for (int j = 0; j < 10; j++) a += o1[j] * cW4[j * 7 + c];
        l[c] = a;
    }

    float m = l[0];
    #pragma unroll
    for (int c = 1; c < 7; c++) m = fmaxf(m, l[c]);
    float ex[7];
    float sum = 0.f;
    #pragma unroll
    for (int c = 0; c < 7; c++) { ex[c] = __expf(l[c] - m); sum += ex[c]; }
    float inv = 1.0f / sum;
    #pragma unroll
    for (int c = 0; c < 7; c++) out[i * 7 + c] = ex[c] * inv;

    if (i == 0 && out_size > N_NODES * 7) {
        out[N_NODES * 7] = (float)g_num;
    }
}

// ---------------- launcher ----------------
extern "C" void kernel_launch(void* const* d_in, const int* in_sizes, int n_in,
                              void* d_out, int out_size)
{
    const float* edge_feat  = (const float*)d_in[0];
    const int*   edge_src   = (const int*)  d_in[1];
    const int*   arc_rows   = (const int*)  d_in[2];
    const float* arc_vals   = (const float*)d_in[3];
    const float* state_init = (const float*)d_in[4];
    const float* old_init   = (const float*)d_in[5];
    const float* W1 = (const float*)d_in[6];
    const float* b1 = (const float*)d_in[7];
    const float* W2 = (const float*)d_in[8];
    const float* b2 = (const float*)d_in[9];
    const float* W3 = (const float*)d_in[10];
    const float* b3 = (const float*)d_in[11];
    const float* W4 = (const float*)d_in[12];
    const float* b4 = (const float*)d_in[13];

    cudaMemcpyToSymbolAsync(cW1a, W1,           8 * 15 * sizeof(float), 0, cudaMemcpyDeviceToDevice, 0);
    cudaMemcpyToSymbolAsync(cW1b, W1 + 8 * 15,  5 * 15 * sizeof(float), 0, cudaMemcpyDeviceToDevice, 0);
    cudaMemcpyToSymbolAsync(cb1,  b1,           15 * sizeof(float),     0, cudaMemcpyDeviceToDevice, 0);
    cudaMemcpyToSymbolAsync(cW2,  W2,           15 * 5 * sizeof(float), 0, cudaMemcpyDeviceToDevice, 0);
    cudaMemcpyToSymbolAsync(cb2,  b2,           5 * sizeof(float),      0, cudaMemcpyDeviceToDevice, 0);
    cudaMemcpyToSymbolAsync(cW3,  W3,           5 * 10 * sizeof(float), 0, cudaMemcpyDeviceToDevice, 0);
    cudaMemcpyToSymbolAsync(cb3,  b3,           10 * sizeof(float),     0, cudaMemcpyDeviceToDevice, 0);
    cudaMemcpyToSymbolAsync(cW4,  W4,           10 * 7 * sizeof(float), 0, cudaMemcpyDeviceToDevice, 0);
    cudaMemcpyToSymbolAsync(cb4,  b4,           7 * sizeof(float),      0, cudaMemcpyDeviceToDevice, 0);

    const int NODE_BLOCKS = (N_NODES + 255) / 256;
    const int EDGE_BLOCKS = (N_EDGES + 255) / 256;   // exactly 6250
    const int SCAN_BLOCKS = (N_NODES + 1023) / 1024; // 98

    init_flags_kernel<<<1, 64>>>();
    init_nodes_kernel<<<NODE_BLOCKS, 256>>>(state_init, old_init);

    // one-time counting sort by arc_rows + F precompute in sorted order
    hist_kernel<<<EDGE_BLOCKS, 256>>>(arc_rows);
    scanA_kernel<<<SCAN_BLOCKS, 256>>>();
    scanB_kernel<<<1, 32>>>(SCAN_BLOCKS);
    scanC_kernel<<<SCAN_BLOCKS, 256>>>();
    scatter_precompute_kernel<<<EDGE_BLOCKS, 256>>>(edge_feat, edge_src, arc_rows, arc_vals);

    for (int k = 0; k < MAX_ITER; k++) {
        edge_kernel<<<EDGE_BLOCKS, 256>>>(k);
        update_kernel<<<NODE_BLOCKS, 256>>>(k);
    }

    output_kernel<<<NODE_BLOCKS, 256>>>((float*)d_out, out_size);
}